// round 2
// baseline (speedup 1.0000x reference)
#include <cuda_runtime.h>
#include <cuda_bf16.h>

#define N_LAYERS 4
#define N_PATCH 196
#define BLK_THREADS 448   // 14 warps: one patch row each
#define IMGS_PER_BLK 32

// Staging buffer written by setup kernel, then D2D-copied into constant bank.
__device__ float g_coef[36];
// 36 bilinear coefficients as constant-bank operands (compile-time offsets ->
// FFMA R,R,c[3][imm],R : zero registers, zero extra instructions).
__constant__ float c_coef[36];

// ---------------------------------------------------------------------------
// Setup: fold the entire ansatz (params) into 3x3 bilinear forms.
// Z_j(p0,p1) = sum_{a,b} coef[a][b] * g_a(p0) * g_b(p1),  g = (1, cos p, sin p)
// ---------------------------------------------------------------------------
__global__ void setup_coefs_kernel(const float* __restrict__ params) {
    if (threadIdx.x != 0 || blockIdx.x != 0) return;
    for (int pair = 0; pair < 2; ++pair) {
        float M[4][4] = {{1,0,0,0},{0,1,0,0},{0,0,1,0},{0,0,0,1}};
        for (int l = 0; l < N_LAYERS; ++l) {
            float a = 0.5f * params[l * 4 + 2 * pair];
            float b = 0.5f * params[l * 4 + 2 * pair + 1];
            float ca = cosf(a), sa = sinf(a), cb = cosf(b), sb = sinf(b);
            float Ra[2][2] = {{ca, -sa}, {sa, ca}};
            float Rb[2][2] = {{cb, -sb}, {sb, cb}};
            float R[4][4];
            for (int i = 0; i < 2; i++)
                for (int j = 0; j < 2; j++)
                    for (int k = 0; k < 2; k++)
                        for (int m = 0; m < 2; m++)
                            R[2*i+j][2*k+m] = Ra[i][k] * Rb[j][m];
            float N[4][4];
            for (int r = 0; r < 4; r++)
                for (int c = 0; c < 4; c++) {
                    float s = 0.f;
                    for (int t = 0; t < 4; t++) s += R[r][t] * M[t][c];
                    N[r][c] = s;
                }
            // CX(ctrl=wire0, tgt=wire1): |10> <-> |11>  => swap rows 2,3
            for (int c = 0; c < 4; c++) {
                M[0][c] = N[0][c]; M[1][c] = N[1][c];
                M[2][c] = N[3][c]; M[3][c] = N[2][c];
            }
        }
        // half-angle quadratic -> full-angle basis map
        const float AL[2][2][3] = {
            {{0.5f, 0.5f, 0.f}, {0.f, 0.f, 0.5f}},
            {{0.f, 0.f, 0.5f}, {0.5f, -0.5f, 0.f}}
        };
        for (int jw = 0; jw < 2; ++jw) {
            float Q[4][4];
            for (int r = 0; r < 4; r++)
                for (int c = 0; c < 4; c++) {
                    float s = 0.f;
                    for (int t = 0; t < 4; t++) {
                        float d = (jw == 0) ? ((t < 2) ? 1.f : -1.f)
                                            : ((t & 1) ? -1.f : 1.f);
                        s += d * M[t][r] * M[t][c];
                    }
                    Q[r][c] = s;
                }
            for (int aa = 0; aa < 3; ++aa)
                for (int bb = 0; bb < 3; ++bb) {
                    float s = 0.f;
                    for (int i = 0; i < 2; i++)
                        for (int k = 0; k < 2; k++)
                            for (int j = 0; j < 2; j++)
                                for (int m = 0; m < 2; m++)
                                    s += Q[2*i+j][2*k+m] * AL[i][k][aa] * AL[j][m][bb];
                    g_coef[pair * 18 + jw * 9 + aa * 3 + bb] = s;
                }
        }
    }
}

// ---------------------------------------------------------------------------
// Polynomial sin/cos for p in [0,1):  abs err < 3e-6. No MUFU.
// ---------------------------------------------------------------------------
__device__ __forceinline__ void fsincos01(float p, float& s, float& c) {
    float p2 = p * p;
    s = p * fmaf(p2, fmaf(p2, fmaf(p2, fmaf(p2, 2.7557319e-6f, -1.9841270e-4f),
                                   8.3333333e-3f), -1.6666667e-1f), 1.0f);
    c = fmaf(p2, fmaf(p2, fmaf(p2, fmaf(p2, 2.4801587e-5f, -1.3888889e-3f),
                               4.1666668e-2f), -0.5f), 1.0f);
}

// base must be a literal at each (inlined) call site -> constant-bank operands.
__device__ __forceinline__ float bilin(int base,
                                       float Ca, float Sa, float Cb, float Sb) {
    float t0 = fmaf(c_coef[base + 2], Sb, fmaf(c_coef[base + 1], Cb, c_coef[base + 0]));
    float t1 = fmaf(c_coef[base + 5], Sb, fmaf(c_coef[base + 4], Cb, c_coef[base + 3]));
    float t2 = fmaf(c_coef[base + 8], Sb, fmaf(c_coef[base + 7], Cb, c_coef[base + 6]));
    return fmaf(t2, Sa, fmaf(t1, Ca, t0));
}

// ---------------------------------------------------------------------------
// Main: block = 32 images x 14 warps (one patch row each), smem reduce, softmax
// ---------------------------------------------------------------------------
__global__ void __launch_bounds__(BLK_THREADS, 3)
quanv_kernel(const float* __restrict__ x, const float* __restrict__ W,
             const float* __restrict__ bias, float* __restrict__ out) {
    __shared__ float4 Ws[N_PATCH * 10];       // [p*10 + c] = W[c][4p + 0..3]
    __shared__ float red[14][IMGS_PER_BLK][10];
    __shared__ float logit_s[IMGS_PER_BLK][10];

    const int tid = threadIdx.x;
    // W -> smem, reorganized as float4 per (patch, class)
    for (int j = tid; j < N_PATCH * 40; j += BLK_THREADS) {
        int p = j / 40, r = j % 40;
        int c = r >> 2, w = r & 3;
        ((float*)Ws)[j] = W[c * 784 + p * 4 + w];
    }
    __syncthreads();

    const int warp = tid >> 5, lane = tid & 31;
    const int img = blockIdx.x * IMGS_PER_BLK + lane;
    const float* xi = x + (long)img * 784;
    const int pr = warp;  // patch row 0..13

    float acc[10];
#pragma unroll
    for (int c = 0; c < 10; c++) acc[c] = 0.f;

#pragma unroll 2
    for (int pc = 0; pc < 14; ++pc) {
        const int p = pr * 14 + pc;
        float2 t = *(const float2*)(xi + pr * 56 + pc * 2);        // pixels w0,w1
        float2 u = *(const float2*)(xi + pr * 56 + 28 + pc * 2);   // pixels w2,w3
        float C0, S0, C1, S1, C2, S2, C3, S3;
        fsincos01(t.x, S0, C0);
        fsincos01(t.y, S1, C1);
        fsincos01(u.x, S2, C2);
        fsincos01(u.y, S3, C3);
        float Z0 = bilin( 0, C0, S0, C1, S1);
        float Z1 = bilin( 9, C0, S0, C1, S1);
        float Z2 = bilin(18, C2, S2, C3, S3);
        float Z3 = bilin(27, C2, S2, C3, S3);
        const float4* wp = &Ws[p * 10];
#pragma unroll
        for (int c = 0; c < 10; c++) {
            float4 wv = wp[c];  // broadcast LDS.128 (all lanes same addr)
            acc[c] = fmaf(wv.x, Z0, acc[c]);
            acc[c] = fmaf(wv.y, Z1, acc[c]);
            acc[c] = fmaf(wv.z, Z2, acc[c]);
            acc[c] = fmaf(wv.w, Z3, acc[c]);
        }
    }

#pragma unroll
    for (int c = 0; c < 10; c++) red[warp][lane][c] = acc[c];
    __syncthreads();

    if (tid < IMGS_PER_BLK * 10) {
        int il = tid / 10, c = tid % 10;
        float s = bias[c];
#pragma unroll
        for (int w2 = 0; w2 < 14; w2++) s += red[w2][il][c];
        logit_s[il][c] = s;
    }
    __syncthreads();

    if (tid < IMGS_PER_BLK) {
        float v[10], m = -1e30f;
#pragma unroll
        for (int c = 0; c < 10; c++) { v[c] = logit_s[tid][c]; m = fmaxf(m, v[c]); }
        float se = 0.f;
#pragma unroll
        for (int c = 0; c < 10; c++) se += __expf(v[c] - m);
        float lse = m + __logf(se);
        const long im = (long)blockIdx.x * IMGS_PER_BLK + tid;
#pragma unroll
        for (int c = 0; c < 10; c++) out[im * 10 + c] = v[c] - lse;
    }
}

extern "C" void kernel_launch(void* const* d_in, const int* in_sizes, int n_in,
                              void* d_out, int out_size) {
    const float* x      = (const float*)d_in[0];  // (8192, 784)
    const float* params = (const float*)d_in[1];  // (4, 4)
    const float* W      = (const float*)d_in[2];  // (10, 784)
    const float* bias   = (const float*)d_in[3];  // (10,)
    float* out = (float*)d_out;

    int bsz = in_sizes[0] / 784;
    setup_coefs_kernel<<<1, 1>>>(params);
    // Move coefficients into the constant bank (D2D memcpy node: graph-legal).
    void* src = nullptr;
    cudaGetSymbolAddress(&src, g_coef);
    cudaMemcpyToSymbolAsync(c_coef, src, 36 * sizeof(float), 0,
                            cudaMemcpyDeviceToDevice, 0);
    quanv_kernel<<<bsz / IMGS_PER_BLK, BLK_THREADS>>>(x, W, bias, out);
}

// round 3
// speedup vs baseline: 1.3608x; 1.3608x over previous
#include <cuda_runtime.h>

// ===========================================================================
// Packed f32x2 helpers (sm_103a): one FFMA2 does 2 images' FMA per lane.
// ===========================================================================
struct f2 { unsigned long long v; };
__device__ __forceinline__ f2 f2fma(f2 a, f2 b, f2 c) {
    f2 r; asm("fma.rn.f32x2 %0, %1, %2, %3;" : "=l"(r.v) : "l"(a.v), "l"(b.v), "l"(c.v)); return r;
}
__device__ __forceinline__ f2 f2mul(f2 a, f2 b) {
    f2 r; asm("mul.rn.f32x2 %0, %1, %2;" : "=l"(r.v) : "l"(a.v), "l"(b.v)); return r;
}
__device__ __forceinline__ f2 f2dup(float x) {
    f2 r; asm("mov.b64 %0, {%1, %1};" : "=l"(r.v) : "f"(x)); return r;
}
__device__ __forceinline__ float2 f2unpack(f2 a) {
    float2 t; asm("mov.b64 {%0, %1}, %2;" : "=f"(t.x), "=f"(t.y) : "l"(a.v)); return t;
}

#define N_LAYERS 4
#define XS_LD 66                      // pixel-major row pitch (even -> 8B-aligned LDS.64)
#define XS_FLOATS (7 * 56 * XS_LD)    // 25,872 floats = 103,488 B
#define SMEM_TOTAL (XS_FLOATS * 4 + 64 * 10 * 4)   // + logit_s = 106,048 B
#define XS(r, k, col) (((r) * 56 + (k)) * XS_LD + (col))

// Pre-duplicated constants built by setup kernel:
__device__ float2 g_coef2[36];        // bilinear coefs, both halves equal
__device__ float4 g_Wb[2 * 196 * 10]; // [pair][patch][class] = (wx,wx,wy,wy)

// ===========================================================================
// Setup: fold ansatz into 3x3 bilinear forms (thread 0) + pack W (all threads)
// ===========================================================================
__global__ void setup_kernel(const float* __restrict__ params,
                             const float* __restrict__ W) {
    const int t = threadIdx.x;
    if (t == 0) {
        for (int pair = 0; pair < 2; ++pair) {
            float M[4][4] = {{1,0,0,0},{0,1,0,0},{0,0,1,0},{0,0,0,1}};
            for (int l = 0; l < N_LAYERS; ++l) {
                float a = 0.5f * params[l * 4 + 2 * pair];
                float b = 0.5f * params[l * 4 + 2 * pair + 1];
                float ca = cosf(a), sa = sinf(a), cb = cosf(b), sb = sinf(b);
                float Ra[2][2] = {{ca, -sa}, {sa, ca}};
                float Rb[2][2] = {{cb, -sb}, {sb, cb}};
                float R[4][4];
                for (int i = 0; i < 2; i++)
                    for (int j = 0; j < 2; j++)
                        for (int k = 0; k < 2; k++)
                            for (int m = 0; m < 2; m++)
                                R[2*i+j][2*k+m] = Ra[i][k] * Rb[j][m];
                float N[4][4];
                for (int r = 0; r < 4; r++)
                    for (int c = 0; c < 4; c++) {
                        float s = 0.f;
                        for (int tt = 0; tt < 4; tt++) s += R[r][tt] * M[tt][c];
                        N[r][c] = s;
                    }
                for (int c = 0; c < 4; c++) {   // CX: swap rows 2,3
                    M[0][c] = N[0][c]; M[1][c] = N[1][c];
                    M[2][c] = N[3][c]; M[3][c] = N[2][c];
                }
            }
            const float AL[2][2][3] = {
                {{0.5f, 0.5f, 0.f}, {0.f, 0.f, 0.5f}},
                {{0.f, 0.f, 0.5f}, {0.5f, -0.5f, 0.f}}
            };
            for (int jw = 0; jw < 2; ++jw) {
                float Q[4][4];
                for (int r = 0; r < 4; r++)
                    for (int c = 0; c < 4; c++) {
                        float s = 0.f;
                        for (int tt = 0; tt < 4; tt++) {
                            float d = (jw == 0) ? ((tt < 2) ? 1.f : -1.f)
                                                : ((tt & 1) ? -1.f : 1.f);
                            s += d * M[tt][r] * M[tt][c];
                        }
                        Q[r][c] = s;
                    }
                for (int aa = 0; aa < 3; ++aa)
                    for (int bb = 0; bb < 3; ++bb) {
                        float s = 0.f;
                        for (int i = 0; i < 2; i++)
                            for (int k = 0; k < 2; k++)
                                for (int j = 0; j < 2; j++)
                                    for (int m = 0; m < 2; m++)
                                        s += Q[2*i+j][2*k+m] * AL[i][k][aa] * AL[j][m][bb];
                        g_coef2[pair * 18 + jw * 9 + aa * 3 + bb] = make_float2(s, s);
                    }
            }
        }
    }
    // Pack W: g_Wb[pair*1960 + p*10 + c] = (wx, wx, wy, wy)
    for (int i = t; i < 2 * 196 * 10; i += blockDim.x) {
        int pair = i / 1960, rest = i % 1960, p = rest / 10, c = rest % 10;
        float wx = W[c * 784 + p * 4 + 2 * pair];
        float wy = W[c * 784 + p * 4 + 2 * pair + 1];
        g_Wb[i] = make_float4(wx, wx, wy, wy);
    }
}

// ---------------------------------------------------------------------------
// Packed polynomial sin/cos for p in [0,1): abs err < 3e-6, FMA pipe only.
// ---------------------------------------------------------------------------
__device__ __forceinline__ void fsincos2(f2 p, f2& s, f2& c,
        f2 KS9, f2 KS7, f2 KS5, f2 KS3, f2 K1,
        f2 KC8, f2 KC6, f2 KC4, f2 KC2) {
    f2 p2 = f2mul(p, p);
    s = f2mul(p, f2fma(p2, f2fma(p2, f2fma(p2, f2fma(p2, KS9, KS7), KS5), KS3), K1));
    c = f2fma(p2, f2fma(p2, f2fma(p2, f2fma(p2, KC8, KC6), KC4), KC2), K1);
}

__device__ __forceinline__ f2 bilin2(const f2* q, f2 Ca, f2 Sa, f2 Cb, f2 Sb) {
    f2 t0 = f2fma(q[2], Sb, f2fma(q[1], Cb, q[0]));
    f2 t1 = f2fma(q[5], Sb, f2fma(q[4], Cb, q[3]));
    f2 t2 = f2fma(q[8], Sb, f2fma(q[7], Cb, q[6]));
    return f2fma(t2, Sa, f2fma(t1, Ca, t0));
}

// ===========================================================================
// Main: 448 threads = 14 warps; 64 images/block (lane j -> imgs 2j, 2j+1).
// Warp w = (pair = w&1, row slot = w>>1); two phases cover 14 patch rows.
// x staged pixel-major in smem (coalesced LDG, conflict-free LDS.64 reads).
// ===========================================================================
__global__ void __launch_bounds__(448, 1)
quanv_kernel(const float* __restrict__ x, const float* __restrict__ bias,
             float* __restrict__ out) {
    extern __shared__ __align__(16) float smemf[];
    float*  xs      = smemf;                  // [7][56][XS_LD]
    float2* red     = (float2*)smemf;         // alias, used after compute
    float*  logit_s = smemf + XS_FLOATS;      // [64][10]

    const int tid = threadIdx.x, w = tid >> 5, lane = tid & 31;
    const int pair = w & 1, rslot = w >> 1;
    const long img0 = (long)blockIdx.x * 64;

    const f2 KS9 = f2dup(2.7557319e-6f), KS7 = f2dup(-1.9841270e-4f);
    const f2 KS5 = f2dup(8.3333333e-3f), KS3 = f2dup(-1.6666667e-1f);
    const f2 K1  = f2dup(1.0f);
    const f2 KC8 = f2dup(2.4801587e-5f), KC6 = f2dup(-1.3888889e-3f);
    const f2 KC4 = f2dup(4.1666668e-2f), KC2 = f2dup(-0.5f);

    // This warp's 18 bilinear coefficients (both Z's of its pair), in regs.
    f2 cfb[18];
#pragma unroll
    for (int i = 0; i < 18; ++i)
        cfb[i] = *(const f2*)&g_coef2[pair * 18 + i];

    f2 acc[10];
#pragma unroll
    for (int c = 0; c < 10; ++c) acc[c] = f2dup(0.f);

    const int koff = 28 * pair;

#pragma unroll 1
    for (int phase = 0; phase < 2; ++phase) {
        const int grow = rslot + 7 * phase;   // global patch row
        // ---- stage: warp w loads row-pair `grow` for image half (w&1) ----
        {
            const int h = pair;
            const float* xrow = x + (img0 + 32 * h) * 784 + grow * 56;
            if (lane < 28) {
#pragma unroll 4
                for (int j = 0; j < 32; ++j) {
                    float2 v = *(const float2*)(xrow + (long)j * 784 + 2 * lane);
                    xs[XS(rslot, 2 * lane,     32 * h + j)] = v.x;
                    xs[XS(rslot, 2 * lane + 1, 32 * h + j)] = v.y;
                }
            }
        }
        __syncthreads();
        // ---- compute 14 patches of (pair, grow) for 64 images ----
#pragma unroll 2
        for (int pc = 0; pc < 14; ++pc) {
            f2 pa = *(const f2*)&xs[XS(rslot, koff + 2 * pc,     2 * lane)];
            f2 pb = *(const f2*)&xs[XS(rslot, koff + 2 * pc + 1, 2 * lane)];
            f2 Sa, Ca, Sb, Cb;
            fsincos2(pa, Sa, Ca, KS9, KS7, KS5, KS3, K1, KC8, KC6, KC4, KC2);
            fsincos2(pb, Sb, Cb, KS9, KS7, KS5, KS3, K1, KC8, KC6, KC4, KC2);
            f2 Z0 = bilin2(cfb,     Ca, Sa, Cb, Sb);
            f2 Z1 = bilin2(cfb + 9, Ca, Sa, Cb, Sb);
            const float4* wp = g_Wb + (pair * 196 + grow * 14 + pc) * 10;
#pragma unroll
            for (int c = 0; c < 10; ++c) {
                ulonglong2 wv = *(const ulonglong2*)(wp + c); // (wx,wx | wy,wy)
                f2 wx; wx.v = wv.x;
                f2 wy; wy.v = wv.y;
                acc[c] = f2fma(wx, Z0, f2fma(wy, Z1, acc[c]));
            }
        }
        __syncthreads();
    }

    // ---- reduction: red aliases xs (all reads done) ----
#pragma unroll
    for (int c = 0; c < 10; ++c)
        red[(w * 32 + lane) * 10 + c] = f2unpack(acc[c]);
    __syncthreads();

    if (tid < 320) {
        const int j = tid / 10, c = tid % 10;
        float sx = 0.f, sy = 0.f;
#pragma unroll
        for (int ww = 0; ww < 14; ++ww) {
            float2 t = red[(ww * 32 + j) * 10 + c];
            sx += t.x; sy += t.y;
        }
        const float bc = bias[c];
        logit_s[(2 * j)     * 10 + c] = sx + bc;
        logit_s[(2 * j + 1) * 10 + c] = sy + bc;
    }
    __syncthreads();

    if (tid < 64) {
        float v[10], m = -1e30f;
#pragma unroll
        for (int c = 0; c < 10; ++c) { v[c] = logit_s[tid * 10 + c]; m = fmaxf(m, v[c]); }
        float se = 0.f;
#pragma unroll
        for (int c = 0; c < 10; ++c) se += __expf(v[c] - m);
        const float lse = m + __logf(se);
        const long im = img0 + tid;
#pragma unroll
        for (int c = 0; c < 10; ++c) out[im * 10 + c] = v[c] - lse;
    }
}

extern "C" void kernel_launch(void* const* d_in, const int* in_sizes, int n_in,
                              void* d_out, int out_size) {
    const float* x      = (const float*)d_in[0];  // (8192, 784)
    const float* params = (const float*)d_in[1];  // (4, 4)
    const float* W      = (const float*)d_in[2];  // (10, 784)
    const float* bias   = (const float*)d_in[3];  // (10,)
    float* out = (float*)d_out;

    cudaFuncSetAttribute(quanv_kernel,
                         cudaFuncAttributeMaxDynamicSharedMemorySize, SMEM_TOTAL);
    const int bsz = in_sizes[0] / 784;
    setup_kernel<<<1, 256>>>(params, W);
    quanv_kernel<<<bsz / 64, 448, SMEM_TOTAL>>>(x, bias, out);
}

// round 4
// speedup vs baseline: 1.4890x; 1.0942x over previous
#include <cuda_runtime.h>

// ===========================================================================
// Packed f32x2 helpers (sm_103a).
// ===========================================================================
struct f2 { unsigned long long v; };
__device__ __forceinline__ f2 f2fma(f2 a, f2 b, f2 c) {
    f2 r; asm("fma.rn.f32x2 %0, %1, %2, %3;" : "=l"(r.v) : "l"(a.v), "l"(b.v), "l"(c.v)); return r;
}
__device__ __forceinline__ f2 f2mul(f2 a, f2 b) {
    f2 r; asm("mul.rn.f32x2 %0, %1, %2;" : "=l"(r.v) : "l"(a.v), "l"(b.v)); return r;
}
__device__ __forceinline__ f2 f2dup(float x) {
    f2 r; asm("mov.b64 %0, {%1, %1};" : "=l"(r.v) : "f"(x)); return r;
}
__device__ __forceinline__ float2 f2unpack(f2 a) {
    float2 t; asm("mov.b64 {%0, %1}, %2;" : "=f"(t.x), "=f"(t.y) : "l"(a.v)); return t;
}

#define N_LAYERS 4
#define BLK 640                        // 20 warps = (rslot 0..4, pair, half)
#define XS_LD 66
#define XS_FLOATS (5 * 56 * XS_LD)     // 18480 floats = 73920 B (5 patch rows)
#define WS_FLOATS (2 * 196 * 10 * 4)   // 15680 floats = 62720 B
#define RED_STRIDE 11
#define SMEM_TOTAL ((XS_FLOATS + WS_FLOATS + 64 * 10) * 4)

__device__ float2 g_coef2[36];         // bilinear coefs, both halves equal
__device__ float4 g_Wb[2 * 196 * 10];  // [pair][patch][class] = (wx,wx,wy,wy)

// ===========================================================================
// Setup: fold ansatz into 3x3 bilinear forms + pack W.
// ===========================================================================
__global__ void setup_kernel(const float* __restrict__ params,
                             const float* __restrict__ W) {
    const int t = threadIdx.x;
    if (t == 0) {
        for (int pair = 0; pair < 2; ++pair) {
            float M[4][4] = {{1,0,0,0},{0,1,0,0},{0,0,1,0},{0,0,0,1}};
            for (int l = 0; l < N_LAYERS; ++l) {
                float a = 0.5f * params[l * 4 + 2 * pair];
                float b = 0.5f * params[l * 4 + 2 * pair + 1];
                float ca = cosf(a), sa = sinf(a), cb = cosf(b), sb = sinf(b);
                float Ra[2][2] = {{ca, -sa}, {sa, ca}};
                float Rb[2][2] = {{cb, -sb}, {sb, cb}};
                float R[4][4];
                for (int i = 0; i < 2; i++)
                    for (int j = 0; j < 2; j++)
                        for (int k = 0; k < 2; k++)
                            for (int m = 0; m < 2; m++)
                                R[2*i+j][2*k+m] = Ra[i][k] * Rb[j][m];
                float N[4][4];
                for (int r = 0; r < 4; r++)
                    for (int c = 0; c < 4; c++) {
                        float s = 0.f;
                        for (int tt = 0; tt < 4; tt++) s += R[r][tt] * M[tt][c];
                        N[r][c] = s;
                    }
                for (int c = 0; c < 4; c++) {   // CX: swap rows 2,3
                    M[0][c] = N[0][c]; M[1][c] = N[1][c];
                    M[2][c] = N[3][c]; M[3][c] = N[2][c];
                }
            }
            const float AL[2][2][3] = {
                {{0.5f, 0.5f, 0.f}, {0.f, 0.f, 0.5f}},
                {{0.f, 0.f, 0.5f}, {0.5f, -0.5f, 0.f}}
            };
            for (int jw = 0; jw < 2; ++jw) {
                float Q[4][4];
                for (int r = 0; r < 4; r++)
                    for (int c = 0; c < 4; c++) {
                        float s = 0.f;
                        for (int tt = 0; tt < 4; tt++) {
                            float d = (jw == 0) ? ((tt < 2) ? 1.f : -1.f)
                                                : ((tt & 1) ? -1.f : 1.f);
                            s += d * M[tt][r] * M[tt][c];
                        }
                        Q[r][c] = s;
                    }
                for (int aa = 0; aa < 3; ++aa)
                    for (int bb = 0; bb < 3; ++bb) {
                        float s = 0.f;
                        for (int i = 0; i < 2; i++)
                            for (int k = 0; k < 2; k++)
                                for (int j = 0; j < 2; j++)
                                    for (int m = 0; m < 2; m++)
                                        s += Q[2*i+j][2*k+m] * AL[i][k][aa] * AL[j][m][bb];
                        g_coef2[pair * 18 + jw * 9 + aa * 3 + bb] = make_float2(s, s);
                    }
            }
        }
    }
    for (int i = t; i < 2 * 196 * 10; i += blockDim.x) {
        int pair = i / 1960, rest = i % 1960, p = rest / 10, c = rest % 10;
        float wx = W[c * 784 + p * 4 + 2 * pair];
        float wy = W[c * 784 + p * 4 + 2 * pair + 1];
        g_Wb[i] = make_float4(wx, wx, wy, wy);
    }
}

// deg-7/6 sin/cos for p in [0,1): abs err < 2.5e-5 (tol is 1e-3). FMA only.
__device__ __forceinline__ void fsincos2(f2 p, f2& s, f2& c,
        f2 KS7, f2 KS5, f2 KS3, f2 K1, f2 KC6, f2 KC4, f2 KC2) {
    f2 p2 = f2mul(p, p);
    s = f2mul(p, f2fma(p2, f2fma(p2, f2fma(p2, KS7, KS5), KS3), K1));
    c = f2fma(p2, f2fma(p2, f2fma(p2, KC6, KC4), KC2), K1);
}

__device__ __forceinline__ f2 bilin2(const f2* q, f2 Ca, f2 Sa, f2 Cb, f2 Sb) {
    f2 t0 = f2fma(q[2], Sb, f2fma(q[1], Cb, q[0]));
    f2 t1 = f2fma(q[5], Sb, f2fma(q[4], Cb, q[3]));
    f2 t2 = f2fma(q[8], Sb, f2fma(q[7], Cb, q[6]));
    return f2fma(t2, Sa, f2fma(t1, Ca, t0));
}

// ===========================================================================
// Main: 640 thr = 20 warps = (rslot 0..4, pair, half); 64 images/block;
// 3 phases stage 5/5/4 patch rows into swizzled smem; W broadcast from smem.
// ===========================================================================
__global__ void __launch_bounds__(BLK, 1)
quanv_kernel(const float* __restrict__ x, const float* __restrict__ bias,
             float* __restrict__ out) {
    extern __shared__ __align__(16) float smemf[];
    float*  xs      = smemf;                              // [5][56][XS_LD]
    float4* Ws4     = (float4*)(smemf + XS_FLOATS);       // [2*196*10]
    float*  logit_s = smemf + XS_FLOATS + WS_FLOATS;      // [64][10]
    f2*     red     = (f2*)smemf;                          // alias of xs

    const int tid = threadIdx.x, w = tid >> 5, lane = tid & 31;
    const int rslot = w >> 2, pair = (w >> 1) & 1, half = w & 1;
    const long img0 = (long)blockIdx.x * 64;

    // W -> smem once
    for (int i = tid; i < 2 * 196 * 10; i += BLK) Ws4[i] = g_Wb[i];

    const f2 KS7 = f2dup(-1.9841270e-4f), KS5 = f2dup(8.3333333e-3f);
    const f2 KS3 = f2dup(-1.6666667e-1f), K1 = f2dup(1.0f);
    const f2 KC6 = f2dup(-1.3888889e-3f), KC4 = f2dup(4.1666668e-2f);
    const f2 KC2 = f2dup(-0.5f);

    f2 cfb[18];
#pragma unroll
    for (int i = 0; i < 18; ++i) cfb[i] = *(const f2*)&g_coef2[pair * 18 + i];

    f2 acc[10];
#pragma unroll
    for (int c = 0; c < 10; ++c) acc[c] = f2dup(0.f);

    const int koff = 28 * pair;

#pragma unroll 1
    for (int phase = 0; phase < 3; ++phase) {
        const int grow = 5 * phase + rslot;          // global patch row
        const bool active = (grow < 14);
        // ---- stage: images [32*pair + 16*half .. +16), row grow ----
        if (active && lane < 28) {
            const int k0 = 2 * lane;
            const int sw = lane & 15;                // (k0>>1)&15 swizzle
            const int colbase = 32 * pair + 16 * half;
            float* dst = xs + (rslot * 56 + k0) * XS_LD;
            const float* xrow = x + (img0 + colbase) * 784 + grow * 56;
#pragma unroll 4
            for (int j = 0; j < 16; ++j) {
                float2 v = *(const float2*)(xrow + (long)j * 784 + k0);
                int cpp = 2 * ((((colbase + j) >> 1) ^ sw)) + (j & 1);
                dst[cpp] = v.x;
                dst[XS_LD + cpp] = v.y;
            }
        }
        __syncthreads();
        // ---- compute 7 patch cols of (pair, grow) for 64 images ----
        if (active) {
#pragma unroll 1
            for (int q = 0; q < 7; ++q) {
                const int pc = 7 * half + q;
                const int k = koff + 2 * pc;
                const int sw = (k >> 1) & 15;
                const float* row = xs + (rslot * 56 + k) * XS_LD + 2 * (lane ^ sw);
                f2 pa = *(const f2*)row;
                f2 pb = *(const f2*)(row + XS_LD);
                f2 Sa, Ca, Sb, Cb;
                fsincos2(pa, Sa, Ca, KS7, KS5, KS3, K1, KC6, KC4, KC2);
                fsincos2(pb, Sb, Cb, KS7, KS5, KS3, K1, KC6, KC4, KC2);
                f2 Z0 = bilin2(cfb,     Ca, Sa, Cb, Sb);
                f2 Z1 = bilin2(cfb + 9, Ca, Sa, Cb, Sb);
                const float4* wp = Ws4 + (pair * 196 + grow * 14 + pc) * 10;
#pragma unroll
                for (int c = 0; c < 10; ++c) {
                    ulonglong2 wv = *(const ulonglong2*)(wp + c); // broadcast
                    f2 wx; wx.v = wv.x;
                    f2 wy; wy.v = wv.y;
                    acc[c] = f2fma(wx, Z0, f2fma(wy, Z1, acc[c]));
                }
            }
        }
        __syncthreads();
    }

    // ---- reduce 20 partial accs (red aliases xs; all reads done) ----
#pragma unroll
    for (int c = 0; c < 10; ++c)
        red[(w * 32 + lane) * RED_STRIDE + c] = acc[c];
    __syncthreads();

    if (tid < 320) {
        const int jp = tid / 10, c = tid % 10;
        float sx = 0.f, sy = 0.f;
#pragma unroll
        for (int ww = 0; ww < 20; ++ww) {
            float2 t = f2unpack(red[(ww * 32 + jp) * RED_STRIDE + c]);
            sx += t.x; sy += t.y;
        }
        const float bc = bias[c];
        logit_s[(2 * jp)     * 10 + c] = sx + bc;
        logit_s[(2 * jp + 1) * 10 + c] = sy + bc;
    }
    __syncthreads();

    if (tid < 64) {
        float v[10], m = -1e30f;
#pragma unroll
        for (int c = 0; c < 10; ++c) { v[c] = logit_s[tid * 10 + c]; m = fmaxf(m, v[c]); }
        float se = 0.f;
#pragma unroll
        for (int c = 0; c < 10; ++c) se += __expf(v[c] - m);
        const float lse = m + __logf(se);
        const long im = img0 + tid;
#pragma unroll
        for (int c = 0; c < 10; ++c) out[im * 10 + c] = v[c] - lse;
    }
}

extern "C" void kernel_launch(void* const* d_in, const int* in_sizes, int n_in,
                              void* d_out, int out_size) {
    const float* x      = (const float*)d_in[0];  // (8192, 784)
    const float* params = (const float*)d_in[1];  // (4, 4)
    const float* W      = (const float*)d_in[2];  // (10, 784)
    const float* bias   = (const float*)d_in[3];  // (10,)
    float* out = (float*)d_out;

    cudaFuncSetAttribute(quanv_kernel,
                         cudaFuncAttributeMaxDynamicSharedMemorySize, SMEM_TOTAL);
    const int bsz = in_sizes[0] / 784;
    setup_kernel<<<1, 256>>>(params, W);
    quanv_kernel<<<bsz / 64, BLK, SMEM_TOTAL>>>(x, bias, out);
}